// round 12
// baseline (speedup 1.0000x reference)
#include <cuda_runtime.h>
#include <cuda_bf16.h>
#include <cstdint>

// B=2, M=2048, HID=1024, NH=16, D=64.  Reference has NO softmax =>
//   G_b = h_b^T h_b;  T_b = Wk G_b;  S_bh = T_h Wv_h^T  (64x64 per head);
//   U_b[:,hD:+D] = Wq_h^T S_bh;  Ct_b = Wo U_b^T;  out_b = h_b Ct_b^T.
// K/V projections are never materialized (Gram-matrix factorization).
// All big GEMMs are D = A * B^T with K-major operands on mma.sync bf16,
// fp32 via bf16x3 split: A*B ~= Ah*Bh + Ah*Bl + Al*Bh.
// (tcgen05 unavailable: harness PTX targets compute_103 which rejects it.)

#define HIDD   1024
#define MSEQ   2048
#define NBATCH 2
#define NHEAD  16
#define DHEAD  64

typedef __nv_bfloat16 bf16;

// ---------------- device scratch ----------------
__device__ bf16 g_hh[NBATCH * MSEQ * HIDD], g_hl[NBATCH * MSEQ * HIDD];
__device__ bf16 g_hTh[NBATCH * HIDD * MSEQ], g_hTl[NBATCH * HIDD * MSEQ];
__device__ bf16 g_wkh[HIDD * HIDD], g_wkl[HIDD * HIDD];
__device__ bf16 g_woh[HIDD * HIDD], g_wol[HIDD * HIDD];
__device__ bf16 g_Gh[NBATCH * HIDD * HIDD], g_Gl[NBATCH * HIDD * HIDD];
__device__ float g_T[NBATCH * HIDD * HIDD];
__device__ float g_S[NBATCH * NHEAD * DHEAD * DHEAD];
__device__ bf16 g_Uh[NBATCH * HIDD * HIDD], g_Ul[NBATCH * HIDD * HIDD];
__device__ bf16 g_Cth[NBATCH * HIDD * HIDD], g_Ctl[NBATCH * HIDD * HIDD];

// ---------------- helpers ----------------
__device__ __forceinline__ void split2(float x, bf16& hi, bf16& lo) {
    hi = __float2bfloat16(x);
    lo = __float2bfloat16(x - __bfloat162float(hi));
}

// SW64-style 16B-chunk swizzle for 64-byte rows (conflict-free ldmatrix)
__device__ __forceinline__ uint32_t swz(uint32_t off) {
    return off ^ ((off >> 3) & 0x30);
}

__device__ __forceinline__ void ldsm4(uint32_t* r, uint32_t sa) {
    asm volatile("ldmatrix.sync.aligned.m8n8.x4.shared.b16 {%0,%1,%2,%3}, [%4];"
                 : "=r"(r[0]), "=r"(r[1]), "=r"(r[2]), "=r"(r[3]) : "r"(sa));
}

__device__ __forceinline__ void mma_bf16(float* d, const uint32_t* a,
                                         uint32_t b0, uint32_t b1) {
    asm volatile(
        "mma.sync.aligned.m16n8k16.row.col.f32.bf16.bf16.f32 "
        "{%0,%1,%2,%3}, {%4,%5,%6,%7}, {%8,%9}, {%0,%1,%2,%3};"
        : "+f"(d[0]), "+f"(d[1]), "+f"(d[2]), "+f"(d[3])
        : "r"(a[0]), "r"(a[1]), "r"(a[2]), "r"(a[3]), "r"(b0), "r"(b1));
}

__device__ __forceinline__ void cp16(uint32_t d, const void* s) {
    asm volatile("cp.async.cg.shared.global [%0], [%1], 16;" :: "r"(d), "l"(s));
}

// ---------------- split fp32 -> (hi, lo) bf16 planes ----------------
__global__ __launch_bounds__(256)
void split_kernel(const float4* __restrict__ x, __nv_bfloat162* __restrict__ hi,
                  __nv_bfloat162* __restrict__ lo, int n4) {
    int i = blockIdx.x * 256 + threadIdx.x;
    if (i >= n4) return;
    float4 v = x[i];
    bf16 h0, l0, h1, l1, h2, l2, h3, l3;
    split2(v.x, h0, l0); split2(v.y, h1, l1);
    split2(v.z, h2, l2); split2(v.w, h3, l3);
    hi[2 * i]     = __nv_bfloat162(h0, h1);
    hi[2 * i + 1] = __nv_bfloat162(h2, h3);
    lo[2 * i]     = __nv_bfloat162(l0, l1);
    lo[2 * i + 1] = __nv_bfloat162(l2, l3);
}

// ---------------- transpose + split: h[b][m][k] -> hT planes [b][k][m] -----
__global__ __launch_bounds__(256)
void tsplit_kernel(const float* __restrict__ h) {
    __shared__ float t[32][33];
    const int b = blockIdx.z;
    const int k0 = blockIdx.x * 32, m0 = blockIdx.y * 32;
    const int col = threadIdx.x & 31, rr = threadIdx.x >> 5;   // rr 0..7

    const float* hp = h + ((size_t)b * MSEQ + m0) * HIDD + k0;
#pragma unroll
    for (int s = 0; s < 4; s++)
        t[rr + s * 8][col] = hp[(size_t)(rr + s * 8) * HIDD + col];
    __syncthreads();

    const size_t ob = ((size_t)b * HIDD + k0) * MSEQ + m0;
#pragma unroll
    for (int s = 0; s < 4; s++) {
        int kr = rr + s * 8;
        bf16 hi, lo;
        split2(t[col][kr], hi, lo);
        g_hTh[ob + (size_t)kr * MSEQ + col] = hi;
        g_hTl[ob + (size_t)kr * MSEQ + col] = lo;
    }
}

// ---------------- bf16x3 mma.sync GEMM: D[128x128 tile] = A * B^T ----------
// A [M,K] K-major ld=ldA, B [N,K] K-major ld=ldB. K multiple of 64.
// 3-stage cp.async pipeline, BK=32. 8 warps, warp tile 64x32.
#define TILE_B 8192
#define BUF_B  (4 * TILE_B)            // Ah, Al, Bh, Bl
#define DSM_SIZE (3 * BUF_B + 256)

__device__ __forceinline__ void stage(uint32_t sb, const bf16* g, int ld, int tid) {
#pragma unroll
    for (int i = 0; i < 2; i++) {
        int idx = tid + 256 * i;            // 0..511
        int r = idx >> 2;                   // 0..127
        int c = (idx & 3) * 16;             // 0,16,32,48 bytes
        cp16(sb + swz((uint32_t)(r * 64 + c)),
             (const char*)g + (size_t)r * (ld * 2) + c);
    }
}

template <bool OSPLIT>
__global__ __launch_bounds__(256)
void gemm3(const bf16* __restrict__ Ah, const bf16* __restrict__ Al,
           const bf16* __restrict__ Bh, const bf16* __restrict__ Bl,
           float* __restrict__ Cf, bf16* __restrict__ Ch, bf16* __restrict__ Cl,
           int K, int ldA, int ldB, int ldC, size_t sA, size_t sB, size_t sC)
{
    extern __shared__ char dyn[];
    uint32_t dbase = (uint32_t)__cvta_generic_to_shared(dyn);
    dbase = (dbase + 255u) & ~255u;

    Ah += (size_t)blockIdx.z * sA;  Al += (size_t)blockIdx.z * sA;
    Bh += (size_t)blockIdx.z * sB;  Bl += (size_t)blockIdx.z * sB;
    if (OSPLIT) { Ch += (size_t)blockIdx.z * sC; Cl += (size_t)blockIdx.z * sC; }
    else        { Cf += (size_t)blockIdx.z * sC; }

    const int bm = blockIdx.y * 128;
    const int bn = blockIdx.x * 128;
    const int tid = threadIdx.x;
    const int lane = tid & 31;
    const int wid = tid >> 5;
    const int wm = (wid >> 2) * 64;     // 0, 64
    const int wn = (wid & 3) * 32;      // 0,32,64,96

    float acc[4][4][4];
#pragma unroll
    for (int mi = 0; mi < 4; mi++)
#pragma unroll
        for (int ni = 0; ni < 4; ni++)
#pragma unroll
            for (int r = 0; r < 4; r++) acc[mi][ni][r] = 0.0f;

    const bf16* Am  = Ah + (size_t)bm * ldA;
    const bf16* Alm = Al + (size_t)bm * ldA;
    const bf16* Bm  = Bh + (size_t)bn * ldB;
    const bf16* Blm = Bl + (size_t)bn * ldB;

    const int NIT = K / 32;

    // prologue: stage chunks 0 and 1
#pragma unroll
    for (int p = 0; p < 2; p++) {
        const uint32_t bo = dbase + p * BUF_B;
        const int k0 = p * 32;
        stage(bo,              Am + k0,  ldA, tid);
        stage(bo + TILE_B,     Alm + k0, ldA, tid);
        stage(bo + 2 * TILE_B, Bm + k0,  ldB, tid);
        stage(bo + 3 * TILE_B, Blm + k0, ldB, tid);
        asm volatile("cp.async.commit_group;" ::: "memory");
    }

    for (int it = 0; it < NIT; it++) {
        if (it + 1 < NIT) asm volatile("cp.async.wait_group 1;" ::: "memory");
        else              asm volatile("cp.async.wait_group 0;" ::: "memory");
        __syncthreads();

        // stage chunk it+2 into buffer (it+2)%3 (freed by compute(it-1))
        if (it + 2 < NIT) {
            const uint32_t bo = dbase + ((it + 2) % 3) * BUF_B;
            const int k0 = (it + 2) * 32;
            stage(bo,              Am + k0,  ldA, tid);
            stage(bo + TILE_B,     Alm + k0, ldA, tid);
            stage(bo + 2 * TILE_B, Bm + k0,  ldB, tid);
            stage(bo + 3 * TILE_B, Blm + k0, ldB, tid);
            asm volatile("cp.async.commit_group;" ::: "memory");
        }

        const uint32_t bo = dbase + (it % 3) * BUF_B;
        const int rlane = lane & 15;
        const int kbyte = (lane >> 4) * 16;
#pragma unroll
        for (int kk = 0; kk < 2; kk++) {       // two K=16 steps
            const uint32_t cbyte = kk * 32 + kbyte;
            uint32_t aH[4][4], aL[4][4], bH[2][4], bL[2][4];
#pragma unroll
            for (int mi = 0; mi < 4; mi++) {
                uint32_t off = (uint32_t)((wm + mi * 16 + rlane) * 64) + cbyte;
                ldsm4(aH[mi], bo + swz(off));
                ldsm4(aL[mi], bo + TILE_B + swz(off));
            }
#pragma unroll
            for (int nb = 0; nb < 2; nb++) {
                uint32_t off = (uint32_t)((wn + nb * 16 + rlane) * 64) + cbyte;
                ldsm4(bH[nb], bo + 2 * TILE_B + swz(off));
                ldsm4(bL[nb], bo + 3 * TILE_B + swz(off));
            }
            // plane-major: 16 independent MMAs between accumulator revisits
#pragma unroll
            for (int mi = 0; mi < 4; mi++)
#pragma unroll
                for (int ni = 0; ni < 4; ni++) {
                    const int nb = ni >> 1, sub = ni & 1;
                    mma_bf16(acc[mi][ni], aH[mi], bH[nb][sub], bH[nb][sub + 2]);
                }
#pragma unroll
            for (int mi = 0; mi < 4; mi++)
#pragma unroll
                for (int ni = 0; ni < 4; ni++) {
                    const int nb = ni >> 1, sub = ni & 1;
                    mma_bf16(acc[mi][ni], aH[mi], bL[nb][sub], bL[nb][sub + 2]);
                }
#pragma unroll
            for (int mi = 0; mi < 4; mi++)
#pragma unroll
                for (int ni = 0; ni < 4; ni++) {
                    const int nb = ni >> 1, sub = ni & 1;
                    mma_bf16(acc[mi][ni], aL[mi], bH[nb][sub], bH[nb][sub + 2]);
                }
        }
        __syncthreads();
    }

    // epilogue: c0:(g,2c) c1:(g,2c+1) c2:(g+8,2c) c3:(g+8,2c+1)
    const int g = lane >> 2;
    const int c2 = (lane & 3) * 2;
#pragma unroll
    for (int mi = 0; mi < 4; mi++) {
#pragma unroll
        for (int ni = 0; ni < 4; ni++) {
            int row0 = bm + wm + mi * 16 + g;
            int col  = bn + wn + ni * 8 + c2;
            float* a = acc[mi][ni];
            if (OSPLIT) {
                bf16 h0, l0, h1, l1;
                split2(a[0], h0, l0); split2(a[1], h1, l1);
                *(__nv_bfloat162*)(Ch + (size_t)row0 * ldC + col) = __nv_bfloat162(h0, h1);
                *(__nv_bfloat162*)(Cl + (size_t)row0 * ldC + col) = __nv_bfloat162(l0, l1);
                split2(a[2], h0, l0); split2(a[3], h1, l1);
                *(__nv_bfloat162*)(Ch + (size_t)(row0 + 8) * ldC + col) = __nv_bfloat162(h0, h1);
                *(__nv_bfloat162*)(Cl + (size_t)(row0 + 8) * ldC + col) = __nv_bfloat162(l0, l1);
            } else {
                *(float2*)(Cf + (size_t)row0 * ldC + col)       = make_float2(a[0], a[1]);
                *(float2*)(Cf + (size_t)(row0 + 8) * ldC + col) = make_float2(a[2], a[3]);
            }
        }
    }
}

// ---------------- S: S_bh[i,j] = sum_q T_b[h*64+i,q] * Wv[h*64+j,q] --------
__global__ __launch_bounds__(256)
void st_kernel(const float* __restrict__ Wv)
{
    const int bh = blockIdx.x;
    const int b = bh >> 4, h = bh & 15;
    const float* Tp = g_T + (size_t)b * HIDD * HIDD + (size_t)(h * DHEAD) * HIDD;
    const float* Wp = Wv + (size_t)(h * DHEAD) * HIDD;

    __shared__ float Ts[32][68];
    __shared__ float Ws[32][68];

    const int tid = threadIdx.x;
    const int i4 = (tid & 15) * 4, j4 = (tid >> 4) * 4;

    float acc[4][4];
#pragma unroll
    for (int i = 0; i < 4; i++)
#pragma unroll
        for (int j = 0; j < 4; j++) acc[i][j] = 0.0f;

    for (int k0 = 0; k0 < HIDD; k0 += 32) {
#pragma unroll
        for (int s = 0; s < 2; s++) {
            int idx = tid + 256 * s;          // 0..511
            int i = idx >> 3;                 // 0..63 (row)
            int c4 = (idx & 7) * 4;           // 0..28 (k)
            float4 tv = *(const float4*)(Tp + (size_t)i * HIDD + k0 + c4);
            Ts[c4 + 0][i] = tv.x; Ts[c4 + 1][i] = tv.y;
            Ts[c4 + 2][i] = tv.z; Ts[c4 + 3][i] = tv.w;
            float4 wv = *(const float4*)(Wp + (size_t)i * HIDD + k0 + c4);
            Ws[c4 + 0][i] = wv.x; Ws[c4 + 1][i] = wv.y;
            Ws[c4 + 2][i] = wv.z; Ws[c4 + 3][i] = wv.w;
        }
        __syncthreads();
#pragma unroll 8
        for (int kk = 0; kk < 32; kk++) {
            float tf[4], vf[4];
            *(float4*)tf = *(const float4*)&Ts[kk][i4];
            *(float4*)vf = *(const float4*)&Ws[kk][j4];
#pragma unroll
            for (int i = 0; i < 4; i++)
#pragma unroll
                for (int j = 0; j < 4; j++) acc[i][j] += tf[i] * vf[j];
        }
        __syncthreads();
    }

    float* Sp = g_S + (size_t)bh * (DHEAD * DHEAD);
#pragma unroll
    for (int i = 0; i < 4; i++)
        *(float4*)(Sp + (size_t)(i4 + i) * DHEAD + j4) =
            make_float4(acc[i][0], acc[i][1], acc[i][2], acc[i][3]);
}

// ---------------- U: U[b][k][h*64+j] = sum_i Wq[h*64+i][k]*S_bh[i][j] ------
__global__ __launch_bounds__(256)
void u_kernel(const float* __restrict__ Wq)
{
    const int bh = blockIdx.x;
    const int b = bh >> 4, h = bh & 15;
    const int k = blockIdx.y * 256 + threadIdx.x;
    const int j0 = blockIdx.z * 32;

    __shared__ float Ss[DHEAD][32];
    for (int e = threadIdx.x; e < DHEAD * 32; e += 256) {
        int i = e >> 5, j = e & 31;
        Ss[i][j] = g_S[(size_t)bh * (DHEAD * DHEAD) + i * DHEAD + j0 + j];
    }
    __syncthreads();

    float acc[32];
#pragma unroll
    for (int j = 0; j < 32; j++) acc[j] = 0.0f;

#pragma unroll 4
    for (int i = 0; i < DHEAD; i++) {
        float w = Wq[(size_t)(h * DHEAD + i) * HIDD + k];
#pragma unroll
        for (int j = 0; j < 32; j += 4) {
            float4 sv = *(const float4*)&Ss[i][j];
            acc[j + 0] += w * sv.x; acc[j + 1] += w * sv.y;
            acc[j + 2] += w * sv.z; acc[j + 3] += w * sv.w;
        }
    }

    size_t base = ((size_t)b * HIDD + k) * HIDD + h * DHEAD + j0;
#pragma unroll
    for (int j = 0; j < 32; j += 2) {
        bf16 h0, l0, h1, l1;
        split2(acc[j], h0, l0); split2(acc[j + 1], h1, l1);
        *(__nv_bfloat162*)(g_Uh + base + j) = __nv_bfloat162(h0, h1);
        *(__nv_bfloat162*)(g_Ul + base + j) = __nv_bfloat162(l0, l1);
    }
}

// ---------------- launch ----------------
extern "C" void kernel_launch(void* const* d_in, const int* in_sizes, int n_in,
                              void* d_out, int out_size)
{
    const float* h  = (const float*)d_in[0];
    // d_in[1] = key_pe: dead branch in reference, unused.
    const float* Wq = (const float*)d_in[2];
    const float* Wk = (const float*)d_in[3];
    const float* Wv = (const float*)d_in[4];
    const float* Wo = (const float*)d_in[5];
    float* out = (float*)d_out;

    bf16 *hh, *hl, *hTh, *hTl, *wkh, *wkl, *woh, *wol, *Gh, *Gl, *Uh, *Ul, *Cth, *Ctl;
    float *Tp;
    cudaGetSymbolAddress((void**)&hh, g_hh);   cudaGetSymbolAddress((void**)&hl, g_hl);
    cudaGetSymbolAddress((void**)&hTh, g_hTh); cudaGetSymbolAddress((void**)&hTl, g_hTl);
    cudaGetSymbolAddress((void**)&wkh, g_wkh); cudaGetSymbolAddress((void**)&wkl, g_wkl);
    cudaGetSymbolAddress((void**)&woh, g_woh); cudaGetSymbolAddress((void**)&wol, g_wol);
    cudaGetSymbolAddress((void**)&Gh, g_Gh);   cudaGetSymbolAddress((void**)&Gl, g_Gl);
    cudaGetSymbolAddress((void**)&Tp, g_T);
    cudaGetSymbolAddress((void**)&Uh, g_Uh);   cudaGetSymbolAddress((void**)&Ul, g_Ul);
    cudaGetSymbolAddress((void**)&Cth, g_Cth); cudaGetSymbolAddress((void**)&Ctl, g_Ctl);

    cudaFuncSetAttribute(gemm3<false>, cudaFuncAttributeMaxDynamicSharedMemorySize, DSM_SIZE);
    cudaFuncSetAttribute(gemm3<true>,  cudaFuncAttributeMaxDynamicSharedMemorySize, DSM_SIZE);

    const dim3 blk(256);
    const size_t HH = (size_t)HIDD * HIDD;    // 1M
    const size_t MH = (size_t)MSEQ * HIDD;    // 2M
    const int nh4 = (NBATCH * MSEQ * HIDD) / 4;
    const int nw4 = (HIDD * HIDD) / 4;

    // input prep
    split_kernel<<<(nh4 + 255) / 256, blk>>>((const float4*)h,
        (__nv_bfloat162*)hh, (__nv_bfloat162*)hl, nh4);
    tsplit_kernel<<<dim3(HIDD / 32, MSEQ / 32, NBATCH), blk>>>(h);
    split_kernel<<<(nw4 + 255) / 256, blk>>>((const float4*)Wk,
        (__nv_bfloat162*)wkh, (__nv_bfloat162*)wkl, nw4);
    split_kernel<<<(nw4 + 255) / 256, blk>>>((const float4*)Wo,
        (__nv_bfloat162*)woh, (__nv_bfloat162*)wol, nw4);

    // G_b = hT_b * hT_b^T  (1024x1024 per batch, K=2048) -> bf16 planes
    gemm3<true><<<dim3(HIDD / 128, HIDD / 128, NBATCH), blk, DSM_SIZE>>>(
        hTh, hTl, hTh, hTl, nullptr, Gh, Gl,
        MSEQ, MSEQ, MSEQ, HIDD, MH, MH, HH);

    // T_b = Wk * G_b (symmetric G => A*B^T form) -> fp32
    gemm3<false><<<dim3(HIDD / 128, HIDD / 128, NBATCH), blk, DSM_SIZE>>>(
        wkh, wkl, Gh, Gl, Tp, nullptr, nullptr,
        HIDD, HIDD, HIDD, HIDD, 0, HH, HH);

    // S_bh = T_h * Wv_h^T (fp32, small)
    st_kernel<<<dim3(NBATCH * NHEAD), blk>>>(Wv);

    // U (fp32 compute, bf16 hi/lo planes out)
    u_kernel<<<dim3(NBATCH * NHEAD, HIDD / 256, 2), blk>>>(Wq);

    // Ct_b[n,k] = sum_j Wo[n,j] U_b[k,j] -> bf16 planes
    gemm3<true><<<dim3(HIDD / 128, HIDD / 128, NBATCH), blk, DSM_SIZE>>>(
        woh, wol, Uh, Ul, nullptr, Cth, Ctl,
        HIDD, HIDD, HIDD, HIDD, 0, HH, HH);

    // out_b[m,n] = sum_k h_b[m,k] Ct_b[n,k]
    gemm3<false><<<dim3(HIDD / 128, MSEQ / 128, NBATCH), blk, DSM_SIZE>>>(
        hh, hl, Cth, Ctl, out, nullptr, nullptr,
        HIDD, HIDD, HIDD, HIDD, MH, HH, MH);
}

// round 13
// speedup vs baseline: 1.1144x; 1.1144x over previous
#include <cuda_runtime.h>
#include <cuda_bf16.h>
#include <cstdint>

// B=2, M=2048, HID=1024, NH=16, D=64.  Reference has NO softmax =>
//   G_b = h_b^T h_b (symmetric);  T_b = Wk G_b;  S_bh = T_h Wv_h^T;
//   U_b[:,hD:+D] = Wq_h^T S_bh;  Ct_b = Wo U_b^T;  out_b = h_b Ct_b^T.
// G computed triangular (36/64 tiles) + split-K(2) for full-wave occupancy.
// All big GEMMs are D = A * B^T, K-major, mma.sync bf16 (tcgen05 rejected by
// harness's compute_103 PTX target), fp32 via bf16x3:
//   A*B ~= Ah*Bh + Ah*Bl + Al*Bh.

#define HIDD   1024
#define MSEQ   2048
#define NBATCH 2
#define NHEAD  16
#define DHEAD  64

typedef __nv_bfloat16 bf16;

// ---------------- device scratch ----------------
__device__ bf16 g_hh[NBATCH * MSEQ * HIDD], g_hl[NBATCH * MSEQ * HIDD];
__device__ bf16 g_hTh[NBATCH * HIDD * MSEQ], g_hTl[NBATCH * HIDD * MSEQ];
__device__ bf16 g_wkh[HIDD * HIDD], g_wkl[HIDD * HIDD];
__device__ bf16 g_woh[HIDD * HIDD], g_wol[HIDD * HIDD];
__device__ float g_Gp[4 * HIDD * HIDD];               // [s*2+b] fp32 partials
__device__ bf16 g_Gh[NBATCH * HIDD * HIDD], g_Gl[NBATCH * HIDD * HIDD];
__device__ float g_T[NBATCH * HIDD * HIDD];
__device__ float g_S[NBATCH * NHEAD * DHEAD * DHEAD];
__device__ bf16 g_Uh[NBATCH * HIDD * HIDD], g_Ul[NBATCH * HIDD * HIDD];
__device__ bf16 g_Cth[NBATCH * HIDD * HIDD], g_Ctl[NBATCH * HIDD * HIDD];

// ---------------- helpers ----------------
__device__ __forceinline__ void split2(float x, bf16& hi, bf16& lo) {
    hi = __float2bfloat16(x);
    lo = __float2bfloat16(x - __bfloat162float(hi));
}

__device__ __forceinline__ uint32_t swz(uint32_t off) {
    return off ^ ((off >> 3) & 0x30);
}

__device__ __forceinline__ void ldsm4(uint32_t* r, uint32_t sa) {
    asm volatile("ldmatrix.sync.aligned.m8n8.x4.shared.b16 {%0,%1,%2,%3}, [%4];"
                 : "=r"(r[0]), "=r"(r[1]), "=r"(r[2]), "=r"(r[3]) : "r"(sa));
}

__device__ __forceinline__ void mma_bf16(float* d, const uint32_t* a,
                                         uint32_t b0, uint32_t b1) {
    asm volatile(
        "mma.sync.aligned.m16n8k16.row.col.f32.bf16.bf16.f32 "
        "{%0,%1,%2,%3}, {%4,%5,%6,%7}, {%8,%9}, {%0,%1,%2,%3};"
        : "+f"(d[0]), "+f"(d[1]), "+f"(d[2]), "+f"(d[3])
        : "r"(a[0]), "r"(a[1]), "r"(a[2]), "r"(a[3]), "r"(b0), "r"(b1));
}

__device__ __forceinline__ void cp16(uint32_t d, const void* s) {
    asm volatile("cp.async.cg.shared.global [%0], [%1], 16;" :: "r"(d), "l"(s));
}

// ---------------- split fp32 -> (hi, lo) bf16 planes ----------------
__global__ __launch_bounds__(256)
void split_kernel(const float4* __restrict__ x, __nv_bfloat162* __restrict__ hi,
                  __nv_bfloat162* __restrict__ lo, int n4) {
    int i = blockIdx.x * 256 + threadIdx.x;
    if (i >= n4) return;
    float4 v = x[i];
    bf16 h0, l0, h1, l1, h2, l2, h3, l3;
    split2(v.x, h0, l0); split2(v.y, h1, l1);
    split2(v.z, h2, l2); split2(v.w, h3, l3);
    hi[2 * i]     = __nv_bfloat162(h0, h1);
    hi[2 * i + 1] = __nv_bfloat162(h2, h3);
    lo[2 * i]     = __nv_bfloat162(l0, l1);
    lo[2 * i + 1] = __nv_bfloat162(l2, l3);
}

// ---------------- transpose + split: h[b][m][k] -> hT planes [b][k][m] -----
__global__ __launch_bounds__(256)
void tsplit_kernel(const float* __restrict__ h) {
    __shared__ float t[32][33];
    const int b = blockIdx.z;
    const int k0 = blockIdx.x * 32, m0 = blockIdx.y * 32;
    const int col = threadIdx.x & 31, rr = threadIdx.x >> 5;

    const float* hp = h + ((size_t)b * MSEQ + m0) * HIDD + k0;
#pragma unroll
    for (int s = 0; s < 4; s++)
        t[rr + s * 8][col] = hp[(size_t)(rr + s * 8) * HIDD + col];
    __syncthreads();

    const size_t ob = ((size_t)b * HIDD + k0) * MSEQ + m0;
#pragma unroll
    for (int s = 0; s < 4; s++) {
        int kr = rr + s * 8;
        bf16 hi, lo;
        split2(t[col][kr], hi, lo);
        g_hTh[ob + (size_t)kr * MSEQ + col] = hi;
        g_hTl[ob + (size_t)kr * MSEQ + col] = lo;
    }
}

// ---------------- bf16x3 mma.sync GEMM: D[128x128 tile] = A * B^T ----------
// 3-stage cp.async pipeline, BK=32, 8 warps, warp tile 64x32.
// tri_mode: blockIdx.x in [0,36) decodes upper-triangle tile (i<=j).
// zmode=1 (G): z = s*2+b; A,B offset = b*sA + s*1024; C offset = z*sC.
#define TILE_B 8192
#define BUF_B  (4 * TILE_B)
#define DSM_SIZE (3 * BUF_B + 256)

__device__ __forceinline__ void stage(uint32_t sb, const bf16* g, int ld, int tid) {
#pragma unroll
    for (int i = 0; i < 2; i++) {
        int idx = tid + 256 * i;
        int r = idx >> 2;
        int c = (idx & 3) * 16;
        cp16(sb + swz((uint32_t)(r * 64 + c)),
             (const char*)g + (size_t)r * (ld * 2) + c);
    }
}

template <bool OSPLIT>
__global__ __launch_bounds__(256)
void gemm3(const bf16* __restrict__ Ah, const bf16* __restrict__ Al,
           const bf16* __restrict__ Bh, const bf16* __restrict__ Bl,
           float* __restrict__ Cf, bf16* __restrict__ Ch, bf16* __restrict__ Cl,
           int K, int ldA, int ldB, int ldC, size_t sA, size_t sB, size_t sC,
           int tri_mode, int zmode)
{
    extern __shared__ char dyn[];
    uint32_t dbase = (uint32_t)__cvta_generic_to_shared(dyn);
    dbase = (dbase + 255u) & ~255u;

    if (zmode == 1) {
        size_t o = (size_t)(blockIdx.z & 1) * sA + (size_t)(blockIdx.z >> 1) * 1024;
        Ah += o; Al += o; Bh += o; Bl += o;
        Cf += (size_t)blockIdx.z * sC;
    } else {
        Ah += (size_t)blockIdx.z * sA;  Al += (size_t)blockIdx.z * sA;
        Bh += (size_t)blockIdx.z * sB;  Bl += (size_t)blockIdx.z * sB;
        if (OSPLIT) { Ch += (size_t)blockIdx.z * sC; Cl += (size_t)blockIdx.z * sC; }
        else        { Cf += (size_t)blockIdx.z * sC; }
    }

    int bm, bn;
    if (tri_mode) {
        int t = blockIdx.x, i = 0;
        while (t >= 8 - i) { t -= 8 - i; i++; }
        bm = i * 128; bn = (i + t) * 128;
    } else {
        bm = blockIdx.y * 128; bn = blockIdx.x * 128;
    }

    const int tid = threadIdx.x;
    const int lane = tid & 31;
    const int wid = tid >> 5;
    const int wm = (wid >> 2) * 64;
    const int wn = (wid & 3) * 32;

    float acc[4][4][4];
#pragma unroll
    for (int mi = 0; mi < 4; mi++)
#pragma unroll
        for (int ni = 0; ni < 4; ni++)
#pragma unroll
            for (int r = 0; r < 4; r++) acc[mi][ni][r] = 0.0f;

    const bf16* Am  = Ah + (size_t)bm * ldA;
    const bf16* Alm = Al + (size_t)bm * ldA;
    const bf16* Bm  = Bh + (size_t)bn * ldB;
    const bf16* Blm = Bl + (size_t)bn * ldB;

    const int NIT = K / 32;

#pragma unroll
    for (int p = 0; p < 2; p++) {
        const uint32_t bo = dbase + p * BUF_B;
        const int k0 = p * 32;
        stage(bo,              Am + k0,  ldA, tid);
        stage(bo + TILE_B,     Alm + k0, ldA, tid);
        stage(bo + 2 * TILE_B, Bm + k0,  ldB, tid);
        stage(bo + 3 * TILE_B, Blm + k0, ldB, tid);
        asm volatile("cp.async.commit_group;" ::: "memory");
    }

    for (int it = 0; it < NIT; it++) {
        if (it + 1 < NIT) asm volatile("cp.async.wait_group 1;" ::: "memory");
        else              asm volatile("cp.async.wait_group 0;" ::: "memory");
        __syncthreads();

        if (it + 2 < NIT) {
            const uint32_t bo = dbase + ((it + 2) % 3) * BUF_B;
            const int k0 = (it + 2) * 32;
            stage(bo,              Am + k0,  ldA, tid);
            stage(bo + TILE_B,     Alm + k0, ldA, tid);
            stage(bo + 2 * TILE_B, Bm + k0,  ldB, tid);
            stage(bo + 3 * TILE_B, Blm + k0, ldB, tid);
            asm volatile("cp.async.commit_group;" ::: "memory");
        }

        const uint32_t bo = dbase + (it % 3) * BUF_B;
        const int rlane = lane & 15;
        const int kbyte = (lane >> 4) * 16;
#pragma unroll
        for (int kk = 0; kk < 2; kk++) {
            const uint32_t cbyte = kk * 32 + kbyte;
            uint32_t aH[4][4], aL[4][4], bH[2][4], bL[2][4];
#pragma unroll
            for (int mi = 0; mi < 4; mi++) {
                uint32_t off = (uint32_t)((wm + mi * 16 + rlane) * 64) + cbyte;
                ldsm4(aH[mi], bo + swz(off));
                ldsm4(aL[mi], bo + TILE_B + swz(off));
            }
#pragma unroll
            for (int nb = 0; nb < 2; nb++) {
                uint32_t off = (uint32_t)((wn + nb * 16 + rlane) * 64) + cbyte;
                ldsm4(bH[nb], bo + 2 * TILE_B + swz(off));
                ldsm4(bL[nb], bo + 3 * TILE_B + swz(off));
            }
#pragma unroll
            for (int mi = 0; mi < 4; mi++)
#pragma unroll
                for (int ni = 0; ni < 4; ni++) {
                    const int nb = ni >> 1, sub = ni & 1;
                    mma_bf16(acc[mi][ni], aH[mi], bH[nb][sub], bH[nb][sub + 2]);
                }
#pragma unroll
            for (int mi = 0; mi < 4; mi++)
#pragma unroll
                for (int ni = 0; ni < 4; ni++) {
                    const int nb = ni >> 1, sub = ni & 1;
                    mma_bf16(acc[mi][ni], aH[mi], bL[nb][sub], bL[nb][sub + 2]);
                }
#pragma unroll
            for (int mi = 0; mi < 4; mi++)
#pragma unroll
                for (int ni = 0; ni < 4; ni++) {
                    const int nb = ni >> 1, sub = ni & 1;
                    mma_bf16(acc[mi][ni], aL[mi], bH[nb][sub], bH[nb][sub + 2]);
                }
        }
        __syncthreads();
    }

    const int g = lane >> 2;
    const int c2 = (lane & 3) * 2;
#pragma unroll
    for (int mi = 0; mi < 4; mi++) {
#pragma unroll
        for (int ni = 0; ni < 4; ni++) {
            int row0 = bm + wm + mi * 16 + g;
            int col  = bn + wn + ni * 8 + c2;
            float* a = acc[mi][ni];
            if (OSPLIT) {
                bf16 h0, l0, h1, l1;
                split2(a[0], h0, l0); split2(a[1], h1, l1);
                *(__nv_bfloat162*)(Ch + (size_t)row0 * ldC + col) = __nv_bfloat162(h0, h1);
                *(__nv_bfloat162*)(Cl + (size_t)row0 * ldC + col) = __nv_bfloat162(l0, l1);
                split2(a[2], h0, l0); split2(a[3], h1, l1);
                *(__nv_bfloat162*)(Ch + (size_t)(row0 + 8) * ldC + col) = __nv_bfloat162(h0, h1);
                *(__nv_bfloat162*)(Cl + (size_t)(row0 + 8) * ldC + col) = __nv_bfloat162(l0, l1);
            } else {
                *(float2*)(Cf + (size_t)row0 * ldC + col)       = make_float2(a[0], a[1]);
                *(float2*)(Cf + (size_t)(row0 + 8) * ldC + col) = make_float2(a[2], a[3]);
            }
        }
    }
}

// ---------------- G combine: sum split-K partials, split to bf16 planes, ----
// ---------------- mirror (j,i) = (i,j)^T.  grid (36, NBATCH), 256 thr. ------
#define GCOMB_SMEM (128 * 129 * 4)
__global__ __launch_bounds__(256)
void gcomb_kernel()
{
    extern __shared__ float ts[];          // [128][129]
    const int b = blockIdx.y;
    int t = blockIdx.x, i = 0;
    while (t >= 8 - i) { t -= 8 - i; i++; }
    const int j = i + t;
    const size_t HH = (size_t)HIDD * HIDD;
    const int tid = threadIdx.x;

    const float* p0 = g_Gp + (size_t)b * HH       + (size_t)(i * 128) * HIDD + j * 128;
    const float* p1 = g_Gp + (size_t)(2 + b) * HH + (size_t)(i * 128) * HIDD + j * 128;

    for (int idx = tid; idx < 128 * 32; idx += 256) {
        int r = idx >> 5, c4 = (idx & 31) * 4;
        float4 a = *(const float4*)(p0 + (size_t)r * HIDD + c4);
        float4 c = *(const float4*)(p1 + (size_t)r * HIDD + c4);
        ts[r * 129 + c4 + 0] = a.x + c.x;
        ts[r * 129 + c4 + 1] = a.y + c.y;
        ts[r * 129 + c4 + 2] = a.z + c.z;
        ts[r * 129 + c4 + 3] = a.w + c.w;
    }
    __syncthreads();

    bf16* Gh = g_Gh + (size_t)b * HH;
    bf16* Gl = g_Gl + (size_t)b * HH;

    // write tile (i,j)
    {
        const size_t base = (size_t)(i * 128) * HIDD + j * 128;
        for (int idx = tid; idx < 128 * 64; idx += 256) {
            int r = idx >> 6, c2 = (idx & 63) * 2;
            bf16 h0, l0, h1, l1;
            split2(ts[r * 129 + c2], h0, l0);
            split2(ts[r * 129 + c2 + 1], h1, l1);
            *(__nv_bfloat162*)(Gh + base + (size_t)r * HIDD + c2) = __nv_bfloat162(h0, h1);
            *(__nv_bfloat162*)(Gl + base + (size_t)r * HIDD + c2) = __nv_bfloat162(l0, l1);
        }
    }
    // mirror tile (j,i): out[r][c] = ts[c][r]
    if (i != j) {
        const size_t base = (size_t)(j * 128) * HIDD + i * 128;
        for (int idx = tid; idx < 128 * 64; idx += 256) {
            int r = idx >> 6, c2 = (idx & 63) * 2;
            bf16 h0, l0, h1, l1;
            split2(ts[c2 * 129 + r], h0, l0);
            split2(ts[(c2 + 1) * 129 + r], h1, l1);
            *(__nv_bfloat162*)(Gh + base + (size_t)r * HIDD + c2) = __nv_bfloat162(h0, h1);
            *(__nv_bfloat162*)(Gl + base + (size_t)r * HIDD + c2) = __nv_bfloat162(l0, l1);
        }
    }
}

// ---------------- S: S_bh[i,j] = sum_q T_b[h*64+i,q] * Wv[h*64+j,q] --------
__global__ __launch_bounds__(256)
void st_kernel(const float* __restrict__ Wv)
{
    const int bh = blockIdx.x;
    const int b = bh >> 4, h = bh & 15;
    const float* Tp = g_T + (size_t)b * HIDD * HIDD + (size_t)(h * DHEAD) * HIDD;
    const float* Wp = Wv + (size_t)(h * DHEAD) * HIDD;

    __shared__ float Ts[32][68];
    __shared__ float Ws[32][68];

    const int tid = threadIdx.x;
    const int i4 = (tid & 15) * 4, j4 = (tid >> 4) * 4;

    float acc[4][4];
#pragma unroll
    for (int i = 0; i < 4; i++)
#pragma unroll
        for (int j = 0; j < 4; j++) acc[i][j] = 0.0f;

    for (int k0 = 0; k0 < HIDD; k0 += 32) {
#pragma unroll
        for (int s = 0; s < 2; s++) {
            int idx = tid + 256 * s;
            int i = idx >> 3;
            int c4 = (idx & 7) * 4;
            float4 tv = *(const float4*)(Tp + (size_t)i * HIDD + k0 + c4);
            Ts[c4 + 0][i] = tv.x; Ts[c4 + 1][i] = tv.y;
            Ts[c4 + 2][i] = tv.z; Ts[c4 + 3][i] = tv.w;
            float4 wv = *(const float4*)(Wp + (size_t)i * HIDD + k0 + c4);
            Ws[c4 + 0][i] = wv.x; Ws[c4 + 1][i] = wv.y;
            Ws[c4 + 2][i] = wv.z; Ws[c4 + 3][i] = wv.w;
        }
        __syncthreads();
#pragma unroll 8
        for (int kk = 0; kk < 32; kk++) {
            float tf[4], vf[4];
            *(float4*)tf = *(const float4*)&Ts[kk][i4];
            *(float4*)vf = *(const float4*)&Ws[kk][j4];
#pragma unroll
            for (int i = 0; i < 4; i++)
#pragma unroll
                for (int j = 0; j < 4; j++) acc[i][j] += tf[i] * vf[j];
        }
        __syncthreads();
    }

    float* Sp = g_S + (size_t)bh * (DHEAD * DHEAD);
#pragma unroll
    for (int i = 0; i < 4; i++)
        *(float4*)(Sp + (size_t)(i4 + i) * DHEAD + j4) =
            make_float4(acc[i][0], acc[i][1], acc[i][2], acc[i][3]);
}

// ---------------- U: U[b][k][h*64+j] = sum_i Wq[h*64+i][k]*S_bh[i][j] ------
__global__ __launch_bounds__(256)
void u_kernel(const float* __restrict__ Wq)
{
    const int bh = blockIdx.x;
    const int b = bh >> 4, h = bh & 15;
    const int k = blockIdx.y * 256 + threadIdx.x;
    const int j0 = blockIdx.z * 32;

    __shared__ float Ss[DHEAD][32];
    for (int e = threadIdx.x; e < DHEAD * 32; e += 256) {
        int i = e >> 5, j = e & 31;
        Ss[i][j] = g_S[(size_t)bh * (DHEAD * DHEAD) + i * DHEAD + j0 + j];
    }
    __syncthreads();

    float acc[32];
#pragma unroll
    for (int j = 0; j < 32; j++) acc[j] = 0.0f;

#pragma unroll 4
    for (int i = 0; i < DHEAD; i++) {
        float w = Wq[(size_t)(h * DHEAD + i) * HIDD + k];
#pragma unroll
        for (int j = 0; j < 32; j += 4) {
            float4 sv = *(const float4*)&Ss[i][j];
            acc[j + 0] += w * sv.x; acc[j + 1] += w * sv.y;
            acc[j + 2] += w * sv.z; acc[j + 3] += w * sv.w;
        }
    }

    size_t base = ((size_t)b * HIDD + k) * HIDD + h * DHEAD + j0;
#pragma unroll
    for (int j = 0; j < 32; j += 2) {
        bf16 h0, l0, h1, l1;
        split2(acc[j], h0, l0); split2(acc[j + 1], h1, l1);
        *(__nv_bfloat162*)(g_Uh + base + j) = __nv_bfloat162(h0, h1);
        *(__nv_bfloat162*)(g_Ul + base + j) = __nv_bfloat162(l0, l1);
    }
}

// ---------------- launch ----------------
extern "C" void kernel_launch(void* const* d_in, const int* in_sizes, int n_in,
                              void* d_out, int out_size)
{
    const float* h  = (const float*)d_in[0];
    // d_in[1] = key_pe: dead branch in reference, unused.
    const float* Wq = (const float*)d_in[2];
    const float* Wk = (const float*)d_in[3];
    const float* Wv = (const float*)d_in[4];
    const float* Wo = (const float*)d_in[5];
    float* out = (float*)d_out;

    bf16 *hh, *hl, *hTh, *hTl, *wkh, *wkl, *woh, *wol, *Gh, *Gl, *Uh, *Ul, *Cth, *Ctl;
    float *Gpp, *Tp;
    cudaGetSymbolAddress((void**)&hh, g_hh);   cudaGetSymbolAddress((void**)&hl, g_hl);
    cudaGetSymbolAddress((void**)&hTh, g_hTh); cudaGetSymbolAddress((void**)&hTl, g_hTl);
    cudaGetSymbolAddress((void**)&wkh, g_wkh); cudaGetSymbolAddress((void**)&wkl, g_wkl);
    cudaGetSymbolAddress((void**)&woh, g_woh); cudaGetSymbolAddress((void**)&wol, g_wol);
    cudaGetSymbolAddress((void**)&Gpp, g_Gp);
    cudaGetSymbolAddress((void**)&Gh, g_Gh);   cudaGetSymbolAddress((void**)&Gl, g_Gl);
    cudaGetSymbolAddress((void**)&Tp, g_T);
    cudaGetSymbolAddress((void**)&Uh, g_Uh);   cudaGetSymbolAddress((void**)&Ul, g_Ul);
    cudaGetSymbolAddress((void**)&Cth, g_Cth); cudaGetSymbolAddress((void**)&Ctl, g_Ctl);

    cudaFuncSetAttribute(gemm3<false>, cudaFuncAttributeMaxDynamicSharedMemorySize, DSM_SIZE);
    cudaFuncSetAttribute(gemm3<true>,  cudaFuncAttributeMaxDynamicSharedMemorySize, DSM_SIZE);
    cudaFuncSetAttribute(gcomb_kernel, cudaFuncAttributeMaxDynamicSharedMemorySize, GCOMB_SMEM);

    const dim3 blk(256);
    const size_t HH = (size_t)HIDD * HIDD;
    const size_t MH = (size_t)MSEQ * HIDD;
    const int nh4 = (NBATCH * MSEQ * HIDD) / 4;
    const int nw4 = (HIDD * HIDD) / 4;

    // input prep
    split_kernel<<<(nh4 + 255) / 256, blk>>>((const float4*)h,
        (__nv_bfloat162*)hh, (__nv_bfloat162*)hl, nh4);
    tsplit_kernel<<<dim3(HIDD / 32, MSEQ / 32, NBATCH), blk>>>(h);
    split_kernel<<<(nw4 + 255) / 256, blk>>>((const float4*)Wk,
        (__nv_bfloat162*)wkh, (__nv_bfloat162*)wkl, nw4);
    split_kernel<<<(nw4 + 255) / 256, blk>>>((const float4*)Wo,
        (__nv_bfloat162*)woh, (__nv_bfloat162*)wol, nw4);

    // G partials: triangular tiles (36), z = s*2+b (split-K 2 x 1024), fp32
    gemm3<false><<<dim3(36, 1, 4), blk, DSM_SIZE>>>(
        hTh, hTl, hTh, hTl, Gpp, nullptr, nullptr,
        1024, MSEQ, MSEQ, HIDD, MH, MH, HH, /*tri=*/1, /*zmode=*/1);

    // combine partials, split to bf16 planes, mirror lower triangle
    gcomb_kernel<<<dim3(36, NBATCH), blk, GCOMB_SMEM>>>();

    // T_b = Wk * G_b (G symmetric => A*B^T form) -> fp32
    gemm3<false><<<dim3(HIDD / 128, HIDD / 128, NBATCH), blk, DSM_SIZE>>>(
        wkh, wkl, Gh, Gl, Tp, nullptr, nullptr,
        HIDD, HIDD, HIDD, HIDD, 0, HH, HH, 0, 0);

    // S_bh = T_h * Wv_h^T (fp32, small)
    st_kernel<<<dim3(NBATCH * NHEAD), blk>>>(Wv);

    // U (fp32 compute, bf16 hi/lo planes out)
    u_kernel<<<dim3(NBATCH * NHEAD, HIDD / 256, 2), blk>>>(Wq);

    // Ct_b[n,k] = sum_j Wo[n,j] U_b[k,j] -> bf16 planes
    gemm3<true><<<dim3(HIDD / 128, HIDD / 128, NBATCH), blk, DSM_SIZE>>>(
        woh, wol, Uh, Ul, nullptr, Cth, Ctl,
        HIDD, HIDD, HIDD, HIDD, 0, HH, HH, 0, 0);

    // out_b[m,n] = sum_k h_b[m,k] Ct_b[n,k]
    gemm3<false><<<dim3(HIDD / 128, MSEQ / 128, NBATCH), blk, DSM_SIZE>>>(
        hh, hl, Cth, Ctl, out, nullptr, nullptr,
        HIDD, HIDD, HIDD, HIDD, MH, HH, MH, 0, 0);
}

// round 14
// speedup vs baseline: 1.1291x; 1.0132x over previous
#include <cuda_runtime.h>
#include <cuda_bf16.h>
#include <cstdint>

// B=2, M=2048, HID=1024, NH=16, D=64.  Reference has NO softmax =>
//   G_b = h_b^T h_b (symmetric);  T_b = Wk G_b;  S_bh = T_h Wv_h^T;
//   U_b[:,hD:+D] = Wq_h^T S_bh;  Ct_b = Wo U_b^T;  out_b = h_b Ct_b^T.
// G computed triangular (36 tiles) + split-K(2).  All big GEMMs are
// D = A * B^T, K-major, mma.sync bf16 (tcgen05 rejected by the harness's
// compute_103 PTX target), fp32 via bf16x3: A*B ~= Ah*Bh + Ah*Bl + Al*Bh.
// This round: 2-stage pipeline + 128-reg cap => 2 CTAs/SM occupancy.

#define HIDD   1024
#define MSEQ   2048
#define NBATCH 2
#define NHEAD  16
#define DHEAD  64

typedef __nv_bfloat16 bf16;

// ---------------- device scratch ----------------
__device__ bf16 g_hh[NBATCH * MSEQ * HIDD], g_hl[NBATCH * MSEQ * HIDD];
__device__ bf16 g_hTh[NBATCH * HIDD * MSEQ], g_hTl[NBATCH * HIDD * MSEQ];
__device__ bf16 g_wkh[HIDD * HIDD], g_wkl[HIDD * HIDD];
__device__ bf16 g_woh[HIDD * HIDD], g_wol[HIDD * HIDD];
__device__ float g_Gp[4 * HIDD * HIDD];               // [s*2+b] fp32 partials
__device__ bf16 g_Gh[NBATCH * HIDD * HIDD], g_Gl[NBATCH * HIDD * HIDD];
__device__ float g_T[NBATCH * HIDD * HIDD];
__device__ float g_S[NBATCH * NHEAD * DHEAD * DHEAD];
__device__ bf16 g_Uh[NBATCH * HIDD * HIDD], g_Ul[NBATCH * HIDD * HIDD];
__device__ bf16 g_Cth[NBATCH * HIDD * HIDD], g_Ctl[NBATCH * HIDD * HIDD];

// ---------------- helpers ----------------
__device__ __forceinline__ void split2(float x, bf16& hi, bf16& lo) {
    hi = __float2bfloat16(x);
    lo = __float2bfloat16(x - __bfloat162float(hi));
}

__device__ __forceinline__ uint32_t swz(uint32_t off) {
    return off ^ ((off >> 3) & 0x30);
}

__device__ __forceinline__ void ldsm4(uint32_t* r, uint32_t sa) {
    asm volatile("ldmatrix.sync.aligned.m8n8.x4.shared.b16 {%0,%1,%2,%3}, [%4];"
                 : "=r"(r[0]), "=r"(r[1]), "=r"(r[2]), "=r"(r[3]) : "r"(sa));
}

__device__ __forceinline__ void mma_bf16(float* d, const uint32_t* a,
                                         uint32_t b0, uint32_t b1) {
    asm volatile(
        "mma.sync.aligned.m16n8k16.row.col.f32.bf16.bf16.f32 "
        "{%0,%1,%2,%3}, {%4,%5,%6,%7}, {%8,%9}, {%0,%1,%2,%3};"
        : "+f"(d[0]), "+f"(d[1]), "+f"(d[2]), "+f"(d[3])
        : "r"(a[0]), "r"(a[1]), "r"(a[2]), "r"(a[3]), "r"(b0), "r"(b1));
}

__device__ __forceinline__ void cp16(uint32_t d, const void* s) {
    asm volatile("cp.async.cg.shared.global [%0], [%1], 16;" :: "r"(d), "l"(s));
}

// ---------------- split fp32 -> (hi, lo) bf16 planes ----------------
__global__ __launch_bounds__(256)
void split_kernel(const float4* __restrict__ x, __nv_bfloat162* __restrict__ hi,
                  __nv_bfloat162* __restrict__ lo, int n4) {
    int i = blockIdx.x * 256 + threadIdx.x;
    if (i >= n4) return;
    float4 v = x[i];
    bf16 h0, l0, h1, l1, h2, l2, h3, l3;
    split2(v.x, h0, l0); split2(v.y, h1, l1);
    split2(v.z, h2, l2); split2(v.w, h3, l3);
    hi[2 * i]     = __nv_bfloat162(h0, h1);
    hi[2 * i + 1] = __nv_bfloat162(h2, h3);
    lo[2 * i]     = __nv_bfloat162(l0, l1);
    lo[2 * i + 1] = __nv_bfloat162(l2, l3);
}

// ---------------- transpose + split: h[b][m][k] -> hT planes [b][k][m] -----
__global__ __launch_bounds__(256)
void tsplit_kernel(const float* __restrict__ h) {
    __shared__ float t[32][33];
    const int b = blockIdx.z;
    const int k0 = blockIdx.x * 32, m0 = blockIdx.y * 32;
    const int col = threadIdx.x & 31, rr = threadIdx.x >> 5;

    const float* hp = h + ((size_t)b * MSEQ + m0) * HIDD + k0;
#pragma unroll
    for (int s = 0; s < 4; s++)
        t[rr + s * 8][col] = hp[(size_t)(rr + s * 8) * HIDD + col];
    __syncthreads();

    const size_t ob = ((size_t)b * HIDD + k0) * MSEQ + m0;
#pragma unroll
    for (int s = 0; s < 4; s++) {
        int kr = rr + s * 8;
        bf16 hi, lo;
        split2(t[col][kr], hi, lo);
        g_hTh[ob + (size_t)kr * MSEQ + col] = hi;
        g_hTl[ob + (size_t)kr * MSEQ + col] = lo;
    }
}

// ---------------- bf16x3 mma.sync GEMM: D[128x128 tile] = A * B^T ----------
// 2-stage cp.async pipeline, BK=32, 8 warps, warp tile 64x32, 2 CTAs/SM.
// tri_mode: blockIdx.x in [0,36) decodes upper-triangle tile (i<=j).
// zmode=1 (G): z = s*2+b; A,B offset = b*sA + s*1024; C offset = z*sC.
#define TILE_B 8192
#define BUF_B  (4 * TILE_B)
#define DSM_SIZE (2 * BUF_B + 256)

__device__ __forceinline__ void stage(uint32_t sb, const bf16* g, int ld, int tid) {
#pragma unroll
    for (int i = 0; i < 2; i++) {
        int idx = tid + 256 * i;
        int r = idx >> 2;
        int c = (idx & 3) * 16;
        cp16(sb + swz((uint32_t)(r * 64 + c)),
             (const char*)g + (size_t)r * (ld * 2) + c);
    }
}

template <bool OSPLIT>
__global__ __launch_bounds__(256, 2)
void gemm3(const bf16* __restrict__ Ah, const bf16* __restrict__ Al,
           const bf16* __restrict__ Bh, const bf16* __restrict__ Bl,
           float* __restrict__ Cf, bf16* __restrict__ Ch, bf16* __restrict__ Cl,
           int K, int ldA, int ldB, int ldC, size_t sA, size_t sB, size_t sC,
           int tri_mode, int zmode)
{
    extern __shared__ char dyn[];
    uint32_t dbase = (uint32_t)__cvta_generic_to_shared(dyn);
    dbase = (dbase + 255u) & ~255u;

    if (zmode == 1) {
        size_t o = (size_t)(blockIdx.z & 1) * sA + (size_t)(blockIdx.z >> 1) * 1024;
        Ah += o; Al += o; Bh += o; Bl += o;
        Cf += (size_t)blockIdx.z * sC;
    } else {
        Ah += (size_t)blockIdx.z * sA;  Al += (size_t)blockIdx.z * sA;
        Bh += (size_t)blockIdx.z * sB;  Bl += (size_t)blockIdx.z * sB;
        if (OSPLIT) { Ch += (size_t)blockIdx.z * sC; Cl += (size_t)blockIdx.z * sC; }
        else        { Cf += (size_t)blockIdx.z * sC; }
    }

    int bm, bn;
    if (tri_mode) {
        int t = blockIdx.x, i = 0;
        while (t >= 8 - i) { t -= 8 - i; i++; }
        bm = i * 128; bn = (i + t) * 128;
    } else {
        bm = blockIdx.y * 128; bn = blockIdx.x * 128;
    }

    const int tid = threadIdx.x;
    const int lane = tid & 31;
    const int wid = tid >> 5;
    const int wm = (wid >> 2) * 64;
    const int wn = (wid & 3) * 32;

    float acc[4][4][4];
#pragma unroll
    for (int mi = 0; mi < 4; mi++)
#pragma unroll
        for (int ni = 0; ni < 4; ni++)
#pragma unroll
            for (int r = 0; r < 4; r++) acc[mi][ni][r] = 0.0f;

    const bf16* Am  = Ah + (size_t)bm * ldA;
    const bf16* Alm = Al + (size_t)bm * ldA;
    const bf16* Bm  = Bh + (size_t)bn * ldB;
    const bf16* Blm = Bl + (size_t)bn * ldB;

    const int NIT = K / 32;

    // prologue: stage chunk 0 into buffer 0
    stage(dbase,              Am,  ldA, tid);
    stage(dbase + TILE_B,     Alm, ldA, tid);
    stage(dbase + 2 * TILE_B, Bm,  ldB, tid);
    stage(dbase + 3 * TILE_B, Blm, ldB, tid);
    asm volatile("cp.async.commit_group;" ::: "memory");

    for (int it = 0; it < NIT; it++) {
        if (it + 1 < NIT) {
            const uint32_t bo = dbase + ((it + 1) & 1) * BUF_B;
            const int k0 = (it + 1) * 32;
            stage(bo,              Am + k0,  ldA, tid);
            stage(bo + TILE_B,     Alm + k0, ldA, tid);
            stage(bo + 2 * TILE_B, Bm + k0,  ldB, tid);
            stage(bo + 3 * TILE_B, Blm + k0, ldB, tid);
            asm volatile("cp.async.commit_group;" ::: "memory");
            asm volatile("cp.async.wait_group 1;" ::: "memory");
        } else {
            asm volatile("cp.async.wait_group 0;" ::: "memory");
        }
        __syncthreads();

        const uint32_t bo = dbase + (it & 1) * BUF_B;
        const int rlane = lane & 15;
        const int kbyte = (lane >> 4) * 16;
#pragma unroll
        for (int kk = 0; kk < 2; kk++) {
            const uint32_t cbyte = kk * 32 + kbyte;
            uint32_t bH[2][4], bL[2][4];
#pragma unroll
            for (int nb = 0; nb < 2; nb++) {
                uint32_t off = (uint32_t)((wn + nb * 16 + rlane) * 64) + cbyte;
                ldsm4(bH[nb], bo + 2 * TILE_B + swz(off));
                ldsm4(bL[nb], bo + 3 * TILE_B + swz(off));
            }
            // process M in two halves: halves the live A-fragment registers
#pragma unroll
            for (int half = 0; half < 2; half++) {
                uint32_t aH[2][4], aL[2][4];
#pragma unroll
                for (int m2 = 0; m2 < 2; m2++) {
                    uint32_t off =
                        (uint32_t)((wm + (half * 2 + m2) * 16 + rlane) * 64) + cbyte;
                    ldsm4(aH[m2], bo + swz(off));
                    ldsm4(aL[m2], bo + TILE_B + swz(off));
                }
                // plane-major: 8 independent MMAs between accumulator revisits
#pragma unroll
                for (int m2 = 0; m2 < 2; m2++)
#pragma unroll
                    for (int ni = 0; ni < 4; ni++) {
                        const int nb = ni >> 1, sub = ni & 1;
                        mma_bf16(acc[half * 2 + m2][ni], aH[m2],
                                 bH[nb][sub], bH[nb][sub + 2]);
                    }
#pragma unroll
                for (int m2 = 0; m2 < 2; m2++)
#pragma unroll
                    for (int ni = 0; ni < 4; ni++) {
                        const int nb = ni >> 1, sub = ni & 1;
                        mma_bf16(acc[half * 2 + m2][ni], aH[m2],
                                 bL[nb][sub], bL[nb][sub + 2]);
                    }
#pragma unroll
                for (int m2 = 0; m2 < 2; m2++)
#pragma unroll
                    for (int ni = 0; ni < 4; ni++) {
                        const int nb = ni >> 1, sub = ni & 1;
                        mma_bf16(acc[half * 2 + m2][ni], aL[m2],
                                 bH[nb][sub], bH[nb][sub + 2]);
                    }
            }
        }
        __syncthreads();
    }

    const int g = lane >> 2;
    const int c2 = (lane & 3) * 2;
#pragma unroll
    for (int mi = 0; mi < 4; mi++) {
#pragma unroll
        for (int ni = 0; ni < 4; ni++) {
            int row0 = bm + wm + mi * 16 + g;
            int col  = bn + wn + ni * 8 + c2;
            float* a = acc[mi][ni];
            if (OSPLIT) {
                bf16 h0, l0, h1, l1;
                split2(a[0], h0, l0); split2(a[1], h1, l1);
                *(__nv_bfloat162*)(Ch + (size_t)row0 * ldC + col) = __nv_bfloat162(h0, h1);
                *(__nv_bfloat162*)(Cl + (size_t)row0 * ldC + col) = __nv_bfloat162(l0, l1);
                split2(a[2], h0, l0); split2(a[3], h1, l1);
                *(__nv_bfloat162*)(Ch + (size_t)(row0 + 8) * ldC + col) = __nv_bfloat162(h0, h1);
                *(__nv_bfloat162*)(Cl + (size_t)(row0 + 8) * ldC + col) = __nv_bfloat162(l0, l1);
            } else {
                *(float2*)(Cf + (size_t)row0 * ldC + col)       = make_float2(a[0], a[1]);
                *(float2*)(Cf + (size_t)(row0 + 8) * ldC + col) = make_float2(a[2], a[3]);
            }
        }
    }
}

// ---------------- G combine: sum split-K partials, split to bf16 planes, ----
// ---------------- mirror (j,i) = (i,j)^T.  grid (36, NBATCH), 256 thr. ------
#define GCOMB_SMEM (128 * 129 * 4)
__global__ __launch_bounds__(256)
void gcomb_kernel()
{
    extern __shared__ float ts[];          // [128][129]
    const int b = blockIdx.y;
    int t = blockIdx.x, i = 0;
    while (t >= 8 - i) { t -= 8 - i; i++; }
    const int j = i + t;
    const size_t HH = (size_t)HIDD * HIDD;
    const int tid = threadIdx.x;

    const float* p0 = g_Gp + (size_t)b * HH       + (size_t)(i * 128) * HIDD + j * 128;
    const float* p1 = g_Gp + (size_t)(2 + b) * HH + (size_t)(i * 128) * HIDD + j * 128;

    for (int idx = tid; idx < 128 * 32; idx += 256) {
        int r = idx >> 5, c4 = (idx & 31) * 4;
        float4 a = *(const float4*)(p0 + (size_t)r * HIDD + c4);
        float4 c = *(const float4*)(p1 + (size_t)r * HIDD + c4);
        ts[r * 129 + c4 + 0] = a.x + c.x;
        ts[r * 129 + c4 + 1] = a.y + c.y;
        ts[r * 129 + c4 + 2] = a.z + c.z;
        ts[r * 129 + c4 + 3] = a.w + c.w;
    }
    __syncthreads();

    bf16* Gh = g_Gh + (size_t)b * HH;
    bf16* Gl = g_Gl + (size_t)b * HH;

    {
        const size_t base = (size_t)(i * 128) * HIDD + j * 128;
        for (int idx = tid; idx < 128 * 64; idx += 256) {
            int r = idx >> 6, c2 = (idx & 63) * 2;
            bf16 h0, l0, h1, l1;
            split2(ts[r * 129 + c2], h0, l0);
            split2(ts[r * 129 + c2 + 1], h1, l1);
            *(__nv_bfloat162*)(Gh + base + (size_t)r * HIDD + c2) = __nv_bfloat162(h0, h1);
            *(__nv_bfloat162*)(Gl + base + (size_t)r * HIDD + c2) = __nv_bfloat162(l0, l1);
        }
    }
    if (i != j) {
        const size_t base = (size_t)(j * 128) * HIDD + i * 128;
        for (int idx = tid; idx < 128 * 64; idx += 256) {
            int r = idx >> 6, c2 = (idx & 63) * 2;
            bf16 h0, l0, h1, l1;
            split2(ts[c2 * 129 + r], h0, l0);
            split2(ts[(c2 + 1) * 129 + r], h1, l1);
            *(__nv_bfloat162*)(Gh + base + (size_t)r * HIDD + c2) = __nv_bfloat162(h0, h1);
            *(__nv_bfloat162*)(Gl + base + (size_t)r * HIDD + c2) = __nv_bfloat162(l0, l1);
        }
    }
}

// ---------------- S: S_bh[i,j] = sum_q T_b[h*64+i,q] * Wv[h*64+j,q] --------
__global__ __launch_bounds__(256)
void st_kernel(const float* __restrict__ Wv)
{
    const int bh = blockIdx.x;
    const int b = bh >> 4, h = bh & 15;
    const float* Tp = g_T + (size_t)b * HIDD * HIDD + (size_t)(h * DHEAD) * HIDD;
    const float* Wp = Wv + (size_t)(h * DHEAD) * HIDD;

    __shared__ float Ts[32][68];
    __shared__ float Ws[32][68];

    const int tid = threadIdx.x;
    const int i4 = (tid & 15) * 4, j4 = (tid >> 4) * 4;

    float acc[4][4];
#pragma unroll
    for (int i = 0; i < 4; i++)
#pragma unroll
        for (int j = 0; j < 4; j++) acc[i][j] = 0.0f;

    for (int k0 = 0; k0 < HIDD; k0 += 32) {
#pragma unroll
        for (int s = 0; s < 2; s++) {
            int idx = tid + 256 * s;
            int i = idx >> 3;
            int c4 = (idx & 7) * 4;
            float4 tv = *(const float4*)(Tp + (size_t)i * HIDD + k0 + c4);
            Ts[c4 + 0][i] = tv.x; Ts[c4 + 1][i] = tv.y;
            Ts[c4 + 2][i] = tv.z; Ts[c4 + 3][i] = tv.w;
            float4 wv = *(const float4*)(Wp + (size_t)i * HIDD + k0 + c4);
            Ws[c4 + 0][i] = wv.x; Ws[c4 + 1][i] = wv.y;
            Ws[c4 + 2][i] = wv.z; Ws[c4 + 3][i] = wv.w;
        }
        __syncthreads();
#pragma unroll 8
        for (int kk = 0; kk < 32; kk++) {
            float tf[4], vf[4];
            *(float4*)tf = *(const float4*)&Ts[kk][i4];
            *(float4*)vf = *(const float4*)&Ws[kk][j4];
#pragma unroll
            for (int i = 0; i < 4; i++)
#pragma unroll
                for (int j = 0; j < 4; j++) acc[i][j] += tf[i] * vf[j];
        }
        __syncthreads();
    }

    float* Sp = g_S + (size_t)bh * (DHEAD * DHEAD);
#pragma unroll
    for (int i = 0; i < 4; i++)
        *(float4*)(Sp + (size_t)(i4 + i) * DHEAD + j4) =
            make_float4(acc[i][0], acc[i][1], acc[i][2], acc[i][3]);
}

// ---------------- U: U[b][k][h*64+j] = sum_i Wq[h*64+i][k]*S_bh[i][j] ------
__global__ __launch_bounds__(256)
void u_kernel(const float* __restrict__ Wq)
{
    const int bh = blockIdx.x;
    const int b = bh >> 4, h = bh & 15;
    const int k = blockIdx.y * 256 + threadIdx.x;
    const int j0 = blockIdx.z * 32;

    __shared__ float Ss[DHEAD][32];
    for (int e = threadIdx.x; e < DHEAD * 32; e += 256) {
        int i = e >> 5, j = e & 31;
        Ss[i][j] = g_S[(size_t)bh * (DHEAD * DHEAD) + i * DHEAD + j0 + j];
    }
    __syncthreads();

    float acc[32];
#pragma unroll
    for (int j = 0; j < 32; j++) acc[j] = 0.0f;

#pragma unroll 4
    for (int i = 0; i < DHEAD; i++) {
        float w = Wq[(size_t)(h * DHEAD + i) * HIDD + k];
#pragma unroll
        for (int j = 0; j < 32; j += 4) {
            float4 sv = *(const float4*)&Ss[i][j];
            acc[j + 0] += w * sv.x; acc[j + 1] += w * sv.y;
            acc[j + 2] += w * sv.z; acc[j + 3] += w * sv.w;
        }
    }

    size_t base = ((size_t)b * HIDD + k) * HIDD + h * DHEAD + j0;
#pragma unroll
    for (int j = 0; j < 32; j += 2) {
        bf16 h0, l0, h1, l1;
        split2(acc[j], h0, l0); split2(acc[j + 1], h1, l1);
        *(__nv_bfloat162*)(g_Uh + base + j) = __nv_bfloat162(h0, h1);
        *(__nv_bfloat162*)(g_Ul + base + j) = __nv_bfloat162(l0, l1);
    }
}

// ---------------- launch ----------------
extern "C" void kernel_launch(void* const* d_in, const int* in_sizes, int n_in,
                              void* d_out, int out_size)
{
    const float* h  = (const float*)d_in[0];
    // d_in[1] = key_pe: dead branch in reference, unused.
    const float* Wq = (const float*)d_in[2];
    const float* Wk = (const float*)d_in[3];
    const float* Wv = (const float*)d_in[4];
    const float* Wo = (const float*)d_in[5];
    float* out = (float*)d_out;

    bf16 *hh, *hl, *hTh, *hTl, *wkh, *wkl, *woh, *wol, *Gh, *Gl, *Uh, *Ul, *Cth, *Ctl;
    float *Gpp, *Tp;
    cudaGetSymbolAddress((void**)&hh, g_hh);   cudaGetSymbolAddress((void**)&hl, g_hl);
    cudaGetSymbolAddress((void**)&hTh, g_hTh); cudaGetSymbolAddress((void**)&hTl, g_hTl);
    cudaGetSymbolAddress((void**)&wkh, g_wkh); cudaGetSymbolAddress((void**)&wkl, g_wkl);
    cudaGetSymbolAddress((void**)&woh, g_woh); cudaGetSymbolAddress((void**)&wol, g_wol);
    cudaGetSymbolAddress((void**)&Gpp, g_Gp);
    cudaGetSymbolAddress((void**)&Gh, g_Gh);   cudaGetSymbolAddress((void**)&Gl, g_Gl);
    cudaGetSymbolAddress((void**)&Tp, g_T);
    cudaGetSymbolAddress((void**)&Uh, g_Uh);   cudaGetSymbolAddress((void**)&Ul, g_Ul);
    cudaGetSymbolAddress((void**)&Cth, g_Cth); cudaGetSymbolAddress((void**)&Ctl, g_Ctl);

    cudaFuncSetAttribute(gemm3<false>, cudaFuncAttributeMaxDynamicSharedMemorySize, DSM_SIZE);
    cudaFuncSetAttribute(gemm3<true>,  cudaFuncAttributeMaxDynamicSharedMemorySize, DSM_SIZE);
    cudaFuncSetAttribute(gcomb_kernel, cudaFuncAttributeMaxDynamicSharedMemorySize, GCOMB_SMEM);

    const dim3 blk(256);
    const size_t HH = (size_t)HIDD * HIDD;
    const size_t MH = (size_t)MSEQ * HIDD;
    const int nh4 = (NBATCH * MSEQ * HIDD) / 4;
    const int nw4 = (HIDD * HIDD) / 4;

    // input prep
    split_kernel<<<(nh4 + 255) / 256, blk>>>((const float4*)h,
        (__nv_bfloat162*)hh, (__nv_bfloat162*)hl, nh4);
    tsplit_kernel<<<dim3(HIDD / 32, MSEQ / 32, NBATCH), blk>>>(h);
    split_kernel<<<(nw4 + 255) / 256, blk>>>((const float4*)Wk,
        (__nv_bfloat162*)wkh, (__nv_bfloat162*)wkl, nw4);
    split_kernel<<<(nw4 + 255) / 256, blk>>>((const float4*)Wo,
        (__nv_bfloat162*)woh, (__nv_bfloat162*)wol, nw4);

    // G partials: triangular tiles (36), z = s*2+b (split-K 2 x 1024), fp32
    gemm3<false><<<dim3(36, 1, 4), blk, DSM_SIZE>>>(
        hTh, hTl, hTh, hTl, Gpp, nullptr, nullptr,
        1024, MSEQ, MSEQ, HIDD, MH, MH, HH, /*tri=*/1, /*zmode=*/1);

    // combine partials, split to bf16 planes, mirror lower triangle
    gcomb_kernel<<<dim3(36, NBATCH), blk, GCOMB_SMEM>>>();

    // T_b = Wk * G_b (G symmetric => A*B^T form) -> fp32
    gemm3<false><<<dim3(HIDD / 128, HIDD / 128, NBATCH), blk, DSM_SIZE>>>(
        wkh, wkl, Gh, Gl, Tp, nullptr, nullptr,
        HIDD, HIDD, HIDD, HIDD, 0, HH, HH, 0, 0);

    // S_bh = T_h * Wv_h^T (fp32, small)
    st_kernel<<<dim3(NBATCH * NHEAD), blk>>>(Wv);

    // U (fp32 compute, bf16 hi/lo planes out)
    u_kernel<<<dim3(NBATCH * NHEAD, HIDD / 256, 2), blk>>>(Wq);

    // Ct_b[n,k] = sum_j Wo[n,j] U_b[k,j] -> bf16 planes
    gemm3<true><<<dim3(HIDD / 128, HIDD / 128, NBATCH), blk, DSM_SIZE>>>(
        woh, wol, Uh, Ul, nullptr, Cth, Ctl,
        HIDD, HIDD, HIDD, HIDD, 0, HH, HH, 0, 0);

    // out_b[m,n] = sum_k h_b[m,k] Ct_b[n,k]
    gemm3<false><<<dim3(HIDD / 128, MSEQ / 128, NBATCH), blk, DSM_SIZE>>>(
        hh, hl, Cth, Ctl, out, nullptr, nullptr,
        HIDD, HIDD, HIDD, HIDD, MH, HH, MH, 0, 0);
}